// round 2
// baseline (speedup 1.0000x reference)
#include <cuda_runtime.h>

#define NN   20000
#define EE   320000
#define E2T  340000   // EE + NN self loops
#define RT   512
#define HC   256      // H*C

// ---------------- scratch (device globals: allocation-free) ----------------
__device__ float g_xl[NN * HC];
__device__ float g_xr[NN * HC];
__device__ float g_me[NN * HC];     // self-loop edge projection (mean_attr @ We^T)
__device__ float g_re[RT * HC];     // relations @ We^T
__device__ float g_mean[NN * 64];   // per-node mean incoming edge_attr
__device__ float g_alpha[E2T * 4];  // raw attention logits per edge per head
__device__ float g_h1[NN * 64];     // layer-0 output
__device__ int   g_deg[NN];
__device__ int   g_rowptr[NN + 1];
__device__ int   g_cursor[NN];
__device__ int   g_csr[E2T];

// ---------------- init + CSR build ----------------
__global__ void k_zero() {
    int i = blockIdx.x * blockDim.x + threadIdx.x;
    if (i < NN) { g_deg[i] = 0; g_cursor[i] = 0; }
}

__global__ void k_count(const int* __restrict__ ei) {
    int i = blockIdx.x * blockDim.x + threadIdx.x;
    if (i < EE) atomicAdd(&g_deg[ei[EE + i]], 1);
}

__global__ void k_scan() {
    __shared__ int s[1024];
    __shared__ int carry;
    int tid = threadIdx.x;
    if (tid == 0) { carry = 0; g_rowptr[0] = 0; }
    __syncthreads();
    for (int base = 0; base < NN; base += 1024) {
        int i = base + tid;
        int v = (i < NN) ? (g_deg[i] + 1) : 0;   // +1 self loop
        s[tid] = v;
        __syncthreads();
        for (int off = 1; off < 1024; off <<= 1) {
            int t = (tid >= off) ? s[tid - off] : 0;
            __syncthreads();
            s[tid] += t;
            __syncthreads();
        }
        if (i < NN) g_rowptr[i + 1] = carry + s[tid];
        __syncthreads();
        if (tid == 0) carry += s[1023];
        __syncthreads();
    }
}

__global__ void k_scatter(const int* __restrict__ ei) {
    int i = blockIdx.x * blockDim.x + threadIdx.x;
    if (i >= E2T) return;
    int d = (i < EE) ? ei[EE + i] : (i - EE);
    int pos = atomicAdd(&g_cursor[d], 1);
    g_csr[g_rowptr[d] + pos] = i;
}

// sort each segment by edge id -> bitwise-deterministic summation order
__global__ void k_sort() {
    int n = blockIdx.x * blockDim.x + threadIdx.x;
    if (n >= NN) return;
    int beg = g_rowptr[n], end = g_rowptr[n + 1];
    for (int i = beg + 1; i < end; i++) {
        int v = g_csr[i];
        int j = i - 1;
        while (j >= beg && g_csr[j] > v) { g_csr[j + 1] = g_csr[j]; j--; }
        g_csr[j + 1] = v;
    }
}

// mean incoming edge_attr per node (warp per node, no atomics)
__global__ __launch_bounds__(256) void k_mean(const float* __restrict__ rel,
                                              const int* __restrict__ relidx) {
    int w = (blockIdx.x * blockDim.x + threadIdx.x) >> 5;
    int lane = threadIdx.x & 31;
    if (w >= NN) return;
    int beg = g_rowptr[w], end = g_rowptr[w + 1];
    float ax = 0.f, ay = 0.f;
    int deg = 0;
    for (int i = beg; i < end; i++) {
        int e = g_csr[i];
        if (e >= EE) continue;   // skip self-loop slot
        deg++;
        int r = relidx[e];
        float2 v = ((const float2*)(rel + (size_t)r * 64))[lane];
        ax += v.x; ay += v.y;
    }
    float inv = 1.f / (float)(deg > 1 ? deg : 1);
    ((float2*)(g_mean + (size_t)w * 64))[lane] = make_float2(ax * inv, ay * inv);
}

// ---------------- GEMM: out[M,256] = A[M,64] @ W[256,64]^T (+bias) ----------------
// grid = ((M+63)/64, 4); block computes 64 rows x 64 cols; 32KB static smem.
__global__ __launch_bounds__(256) void k_gemm(const float* __restrict__ A,
                                              const float* __restrict__ W,
                                              const float* __restrict__ bias,
                                              float* __restrict__ out, int M) {
    __shared__ float Ws[64][65];   // [k][n_local], padded
    __shared__ float xs[64][64];   // [row_local][k]
    int tid = threadIdx.x;
    int row0 = blockIdx.x * 64;
    int n0 = blockIdx.y * 64;

    // load W tile: Ws[k][n] = W[(n0+n)*64 + k]; coalesced over k
    for (int idx = tid; idx < 64 * 64; idx += 256) {
        int n = idx >> 6, k = idx & 63;
        Ws[k][n] = W[(size_t)(n0 + n) * 64 + k];
    }
    // load A tile
    for (int idx = tid; idx < 64 * 64; idx += 256) {
        int r = idx >> 6, k = idx & 63;
        int m = row0 + r;
        xs[r][k] = (m < M) ? A[(size_t)m * 64 + k] : 0.f;
    }
    __syncthreads();

    int cg = tid & 15;        // col group of 4
    int rg = tid >> 4;        // row group of 4
    int r0 = rg * 4, c0 = cg * 4;
    float acc[4][4] = {};
#pragma unroll 4
    for (int k = 0; k < 64; k++) {
        float xv[4], wv[4];
#pragma unroll
        for (int r = 0; r < 4; r++) xv[r] = xs[r0 + r][k];
#pragma unroll
        for (int c = 0; c < 4; c++) wv[c] = Ws[k][c0 + c];
#pragma unroll
        for (int r = 0; r < 4; r++)
#pragma unroll
            for (int c = 0; c < 4; c++) acc[r][c] += xv[r] * wv[c];
    }
    float4 bv = make_float4(0.f, 0.f, 0.f, 0.f);
    if (bias) bv = *((const float4*)(bias + n0 + c0));
#pragma unroll
    for (int r = 0; r < 4; r++) {
        int m = row0 + r0 + r;
        if (m < M)
            *((float4*)(out + (size_t)m * 256 + n0 + c0)) =
                make_float4(acc[r][0] + bv.x, acc[r][1] + bv.y,
                            acc[r][2] + bv.z, acc[r][3] + bv.w);
    }
}

// ---------------- alpha logits (warp per edge) ----------------
__global__ __launch_bounds__(256) void k_alpha(const int* __restrict__ ei,
                                               const int* __restrict__ relidx,
                                               const float* __restrict__ att) {
    int w = (blockIdx.x * blockDim.x + threadIdx.x) >> 5;
    int lane = threadIdx.x & 31;
    if (w >= E2T) return;
    int s, d;
    const float2* eer;
    if (w < EE) {
        s = ei[w];
        d = ei[EE + w];
        eer = (const float2*)(g_re + (size_t)relidx[w] * HC);
    } else {
        s = d = w - EE;
        eer = (const float2*)(g_me + (size_t)s * HC);
    }
    const float2* xlr = (const float2*)(g_xl + (size_t)s * HC);
    const float2* xrr = (const float2*)(g_xr + (size_t)d * HC);
    const float2* at2 = (const float2*)att;
    float p[4];
#pragma unroll
    for (int h = 0; h < 4; h++) {
        int i = h * 32 + lane;
        float2 a = xlr[i], b = xrr[i], c = eer[i], t = at2[i];
        float mx = a.x + b.x + c.x; mx = mx > 0.f ? mx : 0.2f * mx;
        float my = a.y + b.y + c.y; my = my > 0.f ? my : 0.2f * my;
        p[h] = mx * t.x + my * t.y;
    }
#pragma unroll
    for (int off = 16; off; off >>= 1) {
#pragma unroll
        for (int h = 0; h < 4; h++) p[h] += __shfl_xor_sync(0xffffffffu, p[h], off);
    }
    if (lane == 0)
        *((float4*)(g_alpha + (size_t)w * 4)) = make_float4(p[0], p[1], p[2], p[3]);
}

// ---------------- softmax + aggregation (warp per node, no atomics) ----------------
__global__ __launch_bounds__(256) void k_agg(const int* __restrict__ ei,
                                             const float* __restrict__ bias,
                                             float* __restrict__ out) {
    int w = (blockIdx.x * blockDim.x + threadIdx.x) >> 5;
    int lane = threadIdx.x & 31;
    if (w >= NN) return;
    int beg = g_rowptr[w], end = g_rowptr[w + 1];

    float m0 = -1e30f, m1 = -1e30f, m2 = -1e30f, m3 = -1e30f;
    for (int i = beg + lane; i < end; i += 32) {
        float4 a = *((const float4*)(g_alpha + (size_t)g_csr[i] * 4));
        m0 = fmaxf(m0, a.x); m1 = fmaxf(m1, a.y);
        m2 = fmaxf(m2, a.z); m3 = fmaxf(m3, a.w);
    }
#pragma unroll
    for (int off = 16; off; off >>= 1) {
        m0 = fmaxf(m0, __shfl_xor_sync(0xffffffffu, m0, off));
        m1 = fmaxf(m1, __shfl_xor_sync(0xffffffffu, m1, off));
        m2 = fmaxf(m2, __shfl_xor_sync(0xffffffffu, m2, off));
        m3 = fmaxf(m3, __shfl_xor_sync(0xffffffffu, m3, off));
    }
    float s0 = 0.f, s1 = 0.f, s2 = 0.f, s3 = 0.f;
    for (int i = beg + lane; i < end; i += 32) {
        float4 a = *((const float4*)(g_alpha + (size_t)g_csr[i] * 4));
        s0 += __expf(a.x - m0); s1 += __expf(a.y - m1);
        s2 += __expf(a.z - m2); s3 += __expf(a.w - m3);
    }
#pragma unroll
    for (int off = 16; off; off >>= 1) {
        s0 += __shfl_xor_sync(0xffffffffu, s0, off);
        s1 += __shfl_xor_sync(0xffffffffu, s1, off);
        s2 += __shfl_xor_sync(0xffffffffu, s2, off);
        s3 += __shfl_xor_sync(0xffffffffu, s3, off);
    }
    float i0 = 1.f / s0, i1 = 1.f / s1, i2 = 1.f / s2, i3 = 1.f / s3;

    float acc[8] = {0.f, 0.f, 0.f, 0.f, 0.f, 0.f, 0.f, 0.f};
    for (int i = beg; i < end; i++) {      // sorted order -> deterministic
        int e = g_csr[i];
        int sidx = (e < EE) ? ei[e] : (e - EE);
        float4 a = *((const float4*)(g_alpha + (size_t)e * 4));
        float a0 = __expf(a.x - m0) * i0;
        float a1 = __expf(a.y - m1) * i1;
        float a2 = __expf(a.z - m2) * i2;
        float a3 = __expf(a.w - m3) * i3;
        const float2* xlr = (const float2*)(g_xl + (size_t)sidx * HC);
        float2 v0 = xlr[lane], v1 = xlr[32 + lane], v2 = xlr[64 + lane], v3 = xlr[96 + lane];
        acc[0] += a0 * v0.x; acc[1] += a0 * v0.y;
        acc[2] += a1 * v1.x; acc[3] += a1 * v1.y;
        acc[4] += a2 * v2.x; acc[5] += a2 * v2.y;
        acc[6] += a3 * v3.x; acc[7] += a3 * v3.y;
    }
    float2 bv = ((const float2*)bias)[lane];
    float o0 = (acc[0] + acc[2] + acc[4] + acc[6]) * 0.25f + bv.x;
    float o1 = (acc[1] + acc[3] + acc[5] + acc[7]) * 0.25f + bv.y;
    ((float2*)(out + (size_t)w * 64))[lane] = make_float2(o0, o1);
}

// ---------------- host ----------------
extern "C" void kernel_launch(void* const* d_in, const int* in_sizes, int n_in,
                              void* d_out, int out_size) {
    const float* x         = (const float*)d_in[0];
    const int* ei          = (const int*)d_in[1];
    const float* relations = (const float*)d_in[2];
    const int* relidx      = (const int*)d_in[3];
    const float* Wl[2]  = {(const float*)d_in[4],  (const float*)d_in[11]};
    const float* blv[2] = {(const float*)d_in[5],  (const float*)d_in[12]};
    const float* Wr[2]  = {(const float*)d_in[6],  (const float*)d_in[13]};
    const float* brv[2] = {(const float*)d_in[7],  (const float*)d_in[14]};
    const float* We[2]  = {(const float*)d_in[8],  (const float*)d_in[15]};
    const float* att[2] = {(const float*)d_in[9],  (const float*)d_in[16]};
    const float* bo[2]  = {(const float*)d_in[10], (const float*)d_in[17]};

    void *pxl, *pxr, *pme, *pre, *pmean, *ph1;
    cudaGetSymbolAddress(&pxl, g_xl);
    cudaGetSymbolAddress(&pxr, g_xr);
    cudaGetSymbolAddress(&pme, g_me);
    cudaGetSymbolAddress(&pre, g_re);
    cudaGetSymbolAddress(&pmean, g_mean);
    cudaGetSymbolAddress(&ph1, g_h1);

    k_zero<<<(NN + 255) / 256, 256>>>();
    k_count<<<(EE + 255) / 256, 256>>>(ei);
    k_scan<<<1, 1024>>>();
    k_scatter<<<(E2T + 255) / 256, 256>>>(ei);
    k_sort<<<(NN + 255) / 256, 256>>>();
    k_mean<<<(NN * 32 + 255) / 256, 256>>>(relations, relidx);

    const float* xin = x;
    for (int l = 0; l < 2; l++) {
        dim3 gn((NN + 63) / 64, 4);
        dim3 gr((RT + 63) / 64, 4);
        k_gemm<<<gn, 256>>>(xin, Wl[l], blv[l], (float*)pxl, NN);
        k_gemm<<<gn, 256>>>(xin, Wr[l], brv[l], (float*)pxr, NN);
        k_gemm<<<gn, 256>>>((const float*)pmean, We[l], nullptr, (float*)pme, NN);
        k_gemm<<<gr, 256>>>(relations, We[l], nullptr, (float*)pre, RT);
        k_alpha<<<(E2T + 7) / 8, 256>>>(ei, relidx, att[l]);
        float* outp = (l == 0) ? (float*)ph1 : (float*)d_out;
        k_agg<<<(NN + 7) / 8, 256>>>(ei, bo[l], outp);
        xin = (const float*)ph1;
    }
    if (out_size >= NN * 64 + RT * 64)
        cudaMemcpyAsync((float*)d_out + (size_t)NN * 64, relations,
                        (size_t)RT * 64 * sizeof(float), cudaMemcpyDeviceToDevice);
}

// round 3
// speedup vs baseline: 1.5489x; 1.5489x over previous
#include <cuda_runtime.h>
#include <math_constants.h>

#define NN   20000
#define EE   320000
#define E2T  340000   // EE + NN self loops
#define RT   512
#define HC   256      // H*C

// ---------------- scratch (device globals: allocation-free) ----------------
__device__ float g_xl[NN * HC];
__device__ float g_xr[NN * HC];
__device__ float g_me[NN * HC];     // self-loop edge projection (mean_attr @ We^T)
__device__ float g_re[RT * HC];     // relations @ We^T
__device__ float g_mean[NN * 64];   // per-node mean incoming edge_attr
__device__ float g_h1[NN * 64];     // layer-0 output
__device__ int   g_deg[NN];
__device__ int   g_rowptr[NN + 1];
__device__ int   g_cursor[NN];
__device__ int   g_csr[E2T];

// ---------------- init + CSR build ----------------
__global__ void k_zero() {
    int i = blockIdx.x * blockDim.x + threadIdx.x;
    if (i < NN) { g_deg[i] = 0; g_cursor[i] = 0; }
}

__global__ void k_count(const int* __restrict__ ei) {
    int i = blockIdx.x * blockDim.x + threadIdx.x;
    if (i < EE) atomicAdd(&g_deg[ei[EE + i]], 1);
}

__global__ void k_scan() {
    __shared__ int s[1024];
    __shared__ int carry;
    int tid = threadIdx.x;
    if (tid == 0) { carry = 0; g_rowptr[0] = 0; }
    __syncthreads();
    for (int base = 0; base < NN; base += 1024) {
        int i = base + tid;
        int v = (i < NN) ? (g_deg[i] + 1) : 0;   // +1 self loop
        s[tid] = v;
        __syncthreads();
        for (int off = 1; off < 1024; off <<= 1) {
            int t = (tid >= off) ? s[tid - off] : 0;
            __syncthreads();
            s[tid] += t;
            __syncthreads();
        }
        if (i < NN) g_rowptr[i + 1] = carry + s[tid];
        __syncthreads();
        if (tid == 0) carry += s[1023];
        __syncthreads();
    }
}

__global__ void k_scatter(const int* __restrict__ ei) {
    int i = blockIdx.x * blockDim.x + threadIdx.x;
    if (i >= E2T) return;
    int d = (i < EE) ? ei[EE + i] : (i - EE);
    int pos = atomicAdd(&g_cursor[d], 1);
    g_csr[g_rowptr[d] + pos] = i;
}

// sort each segment by edge id (thread-local buffer -> L1, not global round-trips)
__global__ void k_sort() {
    int n = blockIdx.x * blockDim.x + threadIdx.x;
    if (n >= NN) return;
    int beg = g_rowptr[n], end = g_rowptr[n + 1];
    int len = end - beg;
    if (len <= 128) {
        int buf[128];
        for (int i = 0; i < len; i++) buf[i] = g_csr[beg + i];
        for (int i = 1; i < len; i++) {
            int v = buf[i];
            int j = i - 1;
            while (j >= 0 && buf[j] > v) { buf[j + 1] = buf[j]; j--; }
            buf[j + 1] = v;
        }
        for (int i = 0; i < len; i++) g_csr[beg + i] = buf[i];
    } else {
        for (int i = beg + 1; i < end; i++) {
            int v = g_csr[i];
            int j = i - 1;
            while (j >= beg && g_csr[j] > v) { g_csr[j + 1] = g_csr[j]; j--; }
            g_csr[j + 1] = v;
        }
    }
}

// mean incoming edge_attr per node (warp per node, no atomics)
__global__ __launch_bounds__(256) void k_mean(const float* __restrict__ rel,
                                              const int* __restrict__ relidx) {
    int w = (blockIdx.x * blockDim.x + threadIdx.x) >> 5;
    int lane = threadIdx.x & 31;
    if (w >= NN) return;
    int beg = g_rowptr[w], end = g_rowptr[w + 1];
    float ax = 0.f, ay = 0.f;
    int deg = 0;
    for (int i = beg; i < end; i++) {
        int e = g_csr[i];
        if (e >= EE) continue;   // skip self-loop slot
        deg++;
        int r = relidx[e];
        float2 v = ((const float2*)(rel + (size_t)r * 64))[lane];
        ax += v.x; ay += v.y;
    }
    float inv = 1.f / (float)(deg > 1 ? deg : 1);
    ((float2*)(g_mean + (size_t)w * 64))[lane] = make_float2(ax * inv, ay * inv);
}

// ---------------- GEMM: out[M,256] = A[M,64] @ W[256,64]^T (+bias) ----------------
// grid = ((M+127)/128, 4). 128x64 tile, 256 threads, 8x4 per thread, float4 LDS.
__global__ __launch_bounds__(256) void k_gemm(const float* __restrict__ A,
                                              const float* __restrict__ W,
                                              const float* __restrict__ bias,
                                              float* __restrict__ out, int M) {
    __shared__ float xsT[32][132];   // [k][row], padded (132*4B = 16B-mult)
    __shared__ float Ws[32][68];     // [k][n],   padded (68*4B  = 16B-mult)
    int tid = threadIdx.x;
    int row0 = blockIdx.x * 128, n0 = blockIdx.y * 64;
    int rg = tid >> 4, cg = tid & 15;
    int r0 = rg * 8, c0 = cg * 4;
    float acc[8][4] = {};

    for (int kc = 0; kc < 64; kc += 32) {
        // A chunk: 128 rows x 32 k -> 1024 float4 loads, transposed into xsT
#pragma unroll
        for (int it = 0; it < 4; ++it) {
            int idx = tid + it * 256;       // float4 index 0..1023
            int r = idx >> 3, k4 = idx & 7;
            int m = row0 + r;
            float4 v = (m < M) ? *(const float4*)(A + (size_t)m * 64 + kc + k4 * 4)
                               : make_float4(0.f, 0.f, 0.f, 0.f);
            xsT[k4 * 4 + 0][r] = v.x; xsT[k4 * 4 + 1][r] = v.y;
            xsT[k4 * 4 + 2][r] = v.z; xsT[k4 * 4 + 3][r] = v.w;
        }
        // W chunk: 64 n x 32 k -> 512 float4 loads, transposed into Ws
#pragma unroll
        for (int it = 0; it < 2; ++it) {
            int idx = tid + it * 256;       // 0..511
            int n = idx >> 3, k4 = idx & 7;
            float4 v = *(const float4*)(W + (size_t)(n0 + n) * 64 + kc + k4 * 4);
            Ws[k4 * 4 + 0][n] = v.x; Ws[k4 * 4 + 1][n] = v.y;
            Ws[k4 * 4 + 2][n] = v.z; Ws[k4 * 4 + 3][n] = v.w;
        }
        __syncthreads();
#pragma unroll
        for (int k = 0; k < 32; k++) {
            float4 x0 = *(const float4*)&xsT[k][r0];
            float4 x1 = *(const float4*)&xsT[k][r0 + 4];
            float4 wv = *(const float4*)&Ws[k][c0];
            float xv[8] = {x0.x, x0.y, x0.z, x0.w, x1.x, x1.y, x1.z, x1.w};
#pragma unroll
            for (int r = 0; r < 8; r++) {
                acc[r][0] += xv[r] * wv.x; acc[r][1] += xv[r] * wv.y;
                acc[r][2] += xv[r] * wv.z; acc[r][3] += xv[r] * wv.w;
            }
        }
        __syncthreads();
    }
    float4 bv = make_float4(0.f, 0.f, 0.f, 0.f);
    if (bias) bv = *(const float4*)(bias + n0 + c0);
#pragma unroll
    for (int r = 0; r < 8; r++) {
        int m = row0 + r0 + r;
        if (m < M)
            *((float4*)(out + (size_t)m * 256 + n0 + c0)) =
                make_float4(acc[r][0] + bv.x, acc[r][1] + bv.y,
                            acc[r][2] + bv.z, acc[r][3] + bv.w);
    }
}

// ---------------- fused alpha + online softmax + aggregation ----------------
// warp per dst node. Lane holds channels [4*lane, 4*lane+3] (part A, heads 0/1)
// and [128+4*lane, ...] (part B, heads 2/3). Online (flash) softmax: one pass
// over edges, xl[s] read exactly once.
__global__ __launch_bounds__(256) void k_fused(const int* __restrict__ ei,
                                               const int* __restrict__ relidx,
                                               const float* __restrict__ att,
                                               const float* __restrict__ bias,
                                               float* __restrict__ out) {
    int w = (blockIdx.x * blockDim.x + threadIdx.x) >> 5;
    int lane = threadIdx.x & 31;
    if (w >= NN) return;
    int beg = g_rowptr[w], end = g_rowptr[w + 1];

    // per-lane att vectors
    float4 attA = *(const float4*)(att + ((lane >> 4) * 64) + (lane & 15) * 4);
    float4 attB = *(const float4*)(att + 128 + ((lane >> 4) * 64) + (lane & 15) * 4);

    // xr[d] cached in registers
    const float* xrp = g_xr + (size_t)w * HC;
    float4 xrA = *(const float4*)(xrp + 4 * lane);
    float4 xrB = *(const float4*)(xrp + 128 + 4 * lane);

    float mA = -CUDART_INF_F, mB = -CUDART_INF_F;
    float sA = 0.f, sB = 0.f;
    float4 accA = make_float4(0.f, 0.f, 0.f, 0.f);
    float4 accB = make_float4(0.f, 0.f, 0.f, 0.f);

    for (int i = beg; i < end; i++) {
        int e = g_csr[i];
        int sidx; const float* eep;
        if (e < EE) {
            sidx = ei[e];
            eep = g_re + (size_t)relidx[e] * HC;
        } else {
            sidx = w;
            eep = g_me + (size_t)w * HC;
        }
        const float* xlp = g_xl + (size_t)sidx * HC;
        float4 xlA = *(const float4*)(xlp + 4 * lane);
        float4 xlB = *(const float4*)(xlp + 128 + 4 * lane);
        float4 eeA = *(const float4*)(eep + 4 * lane);
        float4 eeB = *(const float4*)(eep + 128 + 4 * lane);

        // m = lrelu(xl + xr + ee); p = dot(m, att)
        float t, pA, pB;
        t = xlA.x + xrA.x + eeA.x; t = t > 0.f ? t : 0.2f * t; pA  = t * attA.x;
        t = xlA.y + xrA.y + eeA.y; t = t > 0.f ? t : 0.2f * t; pA += t * attA.y;
        t = xlA.z + xrA.z + eeA.z; t = t > 0.f ? t : 0.2f * t; pA += t * attA.z;
        t = xlA.w + xrA.w + eeA.w; t = t > 0.f ? t : 0.2f * t; pA += t * attA.w;
        t = xlB.x + xrB.x + eeB.x; t = t > 0.f ? t : 0.2f * t; pB  = t * attB.x;
        t = xlB.y + xrB.y + eeB.y; t = t > 0.f ? t : 0.2f * t; pB += t * attB.y;
        t = xlB.z + xrB.z + eeB.z; t = t > 0.f ? t : 0.2f * t; pB += t * attB.z;
        t = xlB.w + xrB.w + eeB.w; t = t > 0.f ? t : 0.2f * t; pB += t * attB.w;
        // reduce within 16-lane half (head-local)
#pragma unroll
        for (int off = 1; off < 16; off <<= 1) {
            pA += __shfl_xor_sync(0xffffffffu, pA, off);
            pB += __shfl_xor_sync(0xffffffffu, pB, off);
        }
        // online softmax update, part A
        float nm = fmaxf(mA, pA);
        float scl = __expf(mA - nm);
        float wgt = __expf(pA - nm);
        sA = sA * scl + wgt;
        accA.x = accA.x * scl + wgt * xlA.x;
        accA.y = accA.y * scl + wgt * xlA.y;
        accA.z = accA.z * scl + wgt * xlA.z;
        accA.w = accA.w * scl + wgt * xlA.w;
        mA = nm;
        // part B
        nm = fmaxf(mB, pB);
        scl = __expf(mB - nm);
        wgt = __expf(pB - nm);
        sB = sB * scl + wgt;
        accB.x = accB.x * scl + wgt * xlB.x;
        accB.y = accB.y * scl + wgt * xlB.y;
        accB.z = accB.z * scl + wgt * xlB.z;
        accB.w = accB.w * scl + wgt * xlB.w;
        mB = nm;
    }
    // normalize per head (halves have distinct denominators: divide first)
    float iA = 1.f / sA, iB = 1.f / sB;
    accA.x *= iA; accA.y *= iA; accA.z *= iA; accA.w *= iA;
    accB.x *= iB; accB.y *= iB; accB.z *= iB; accB.w *= iB;
    // combine head0+head1 (A) and head2+head3 (B) across halves
    accA.x += __shfl_xor_sync(0xffffffffu, accA.x, 16);
    accA.y += __shfl_xor_sync(0xffffffffu, accA.y, 16);
    accA.z += __shfl_xor_sync(0xffffffffu, accA.z, 16);
    accA.w += __shfl_xor_sync(0xffffffffu, accA.w, 16);
    accB.x += __shfl_xor_sync(0xffffffffu, accB.x, 16);
    accB.y += __shfl_xor_sync(0xffffffffu, accB.y, 16);
    accB.z += __shfl_xor_sync(0xffffffffu, accB.z, 16);
    accB.w += __shfl_xor_sync(0xffffffffu, accB.w, 16);
    if (lane < 16) {
        float4 bv = *(const float4*)(bias + 4 * lane);
        float4 o;
        o.x = 0.25f * (accA.x + accB.x) + bv.x;
        o.y = 0.25f * (accA.y + accB.y) + bv.y;
        o.z = 0.25f * (accA.z + accB.z) + bv.z;
        o.w = 0.25f * (accA.w + accB.w) + bv.w;
        *(float4*)(out + (size_t)w * 64 + 4 * lane) = o;
    }
}

// ---------------- host ----------------
extern "C" void kernel_launch(void* const* d_in, const int* in_sizes, int n_in,
                              void* d_out, int out_size) {
    const float* x         = (const float*)d_in[0];
    const int* ei          = (const int*)d_in[1];
    const float* relations = (const float*)d_in[2];
    const int* relidx      = (const int*)d_in[3];
    const float* Wl[2]  = {(const float*)d_in[4],  (const float*)d_in[11]};
    const float* blv[2] = {(const float*)d_in[5],  (const float*)d_in[12]};
    const float* Wr[2]  = {(const float*)d_in[6],  (const float*)d_in[13]};
    const float* brv[2] = {(const float*)d_in[7],  (const float*)d_in[14]};
    const float* We[2]  = {(const float*)d_in[8],  (const float*)d_in[15]};
    const float* att[2] = {(const float*)d_in[9],  (const float*)d_in[16]};
    const float* bo[2]  = {(const float*)d_in[10], (const float*)d_in[17]};

    void *pxl, *pxr, *pme, *pre, *pmean, *ph1;
    cudaGetSymbolAddress(&pxl, g_xl);
    cudaGetSymbolAddress(&pxr, g_xr);
    cudaGetSymbolAddress(&pme, g_me);
    cudaGetSymbolAddress(&pre, g_re);
    cudaGetSymbolAddress(&pmean, g_mean);
    cudaGetSymbolAddress(&ph1, g_h1);

    k_zero<<<(NN + 255) / 256, 256>>>();
    k_count<<<(EE + 255) / 256, 256>>>(ei);
    k_scan<<<1, 1024>>>();
    k_scatter<<<(E2T + 255) / 256, 256>>>(ei);
    k_sort<<<(NN + 255) / 256, 256>>>();
    k_mean<<<(NN * 32 + 255) / 256, 256>>>(relations, relidx);

    const float* xin = x;
    for (int l = 0; l < 2; l++) {
        dim3 gn((NN + 127) / 128, 4);
        dim3 gr((RT + 127) / 128, 4);
        k_gemm<<<gn, 256>>>(xin, Wl[l], blv[l], (float*)pxl, NN);
        k_gemm<<<gn, 256>>>(xin, Wr[l], brv[l], (float*)pxr, NN);
        k_gemm<<<gn, 256>>>((const float*)pmean, We[l], nullptr, (float*)pme, NN);
        k_gemm<<<gr, 256>>>(relations, We[l], nullptr, (float*)pre, RT);
        float* outp = (l == 0) ? (float*)ph1 : (float*)d_out;
        k_fused<<<(NN + 7) / 8, 256>>>(ei, relidx, att[l], bo[l], outp);
        xin = (const float*)ph1;
    }
    if (out_size >= NN * 64 + RT * 64)
        cudaMemcpyAsync((float*)d_out + (size_t)NN * 64, relations,
                        (size_t)RT * 64 * sizeof(float), cudaMemcpyDeviceToDevice);
}

// round 4
// speedup vs baseline: 1.9531x; 1.2610x over previous
#include <cuda_runtime.h>
#include <math_constants.h>

#define NN   20000
#define EE   320000
#define RT   512
#define HC   256      // H*C

// ---------------- scratch (device globals: allocation-free) ----------------
__device__ float g_xl[NN * HC];
__device__ float g_xr[NN * HC];
__device__ float g_re[RT * HC];     // relations @ We^T
__device__ float g_h1[NN * 64];     // layer-0 output
__device__ int   g_deg[NN];
__device__ int   g_rowptr[NN + 1];
__device__ int   g_cursor[NN];
__device__ int   g_csr[EE];

// ---------------- init + CSR build (real edges only; self-loop handled in k_fused) ----
__global__ void k_zero() {
    int i = blockIdx.x * blockDim.x + threadIdx.x;
    if (i < NN) { g_deg[i] = 0; g_cursor[i] = 0; }
}

__global__ void k_count(const int* __restrict__ ei) {
    int i = blockIdx.x * blockDim.x + threadIdx.x;
    if (i < EE) atomicAdd(&g_deg[ei[EE + i]], 1);
}

// single-block warp-shuffle scan over g_deg -> g_rowptr
__global__ void k_scan() {
    __shared__ int wsum[32];
    __shared__ int carry;
    int tid = threadIdx.x, lane = tid & 31, wid = tid >> 5;
    if (tid == 0) { carry = 0; g_rowptr[0] = 0; }
    __syncthreads();
    for (int base = 0; base < NN; base += 1024) {
        int i = base + tid;
        int x = (i < NN) ? g_deg[i] : 0;
#pragma unroll
        for (int off = 1; off < 32; off <<= 1) {
            int t = __shfl_up_sync(0xffffffffu, x, off);
            if (lane >= off) x += t;
        }
        if (lane == 31) wsum[wid] = x;
        __syncthreads();
        if (wid == 0) {
            int s = wsum[lane];
#pragma unroll
            for (int off = 1; off < 32; off <<= 1) {
                int t = __shfl_up_sync(0xffffffffu, s, off);
                if (lane >= off) s += t;
            }
            wsum[lane] = s;
        }
        __syncthreads();
        int total = wsum[31];
        int prefix = carry + (wid ? wsum[wid - 1] : 0) + x;   // inclusive
        if (i < NN) g_rowptr[i + 1] = prefix;
        __syncthreads();
        if (tid == 0) carry += total;
        __syncthreads();
    }
}

__global__ void k_scatter(const int* __restrict__ ei) {
    int i = blockIdx.x * blockDim.x + threadIdx.x;
    if (i >= EE) return;
    int d = ei[EE + i];
    int pos = atomicAdd(&g_cursor[d], 1);
    g_csr[g_rowptr[d] + pos] = i;
}

// sort each segment by edge id (thread-local buffer -> L1)
__global__ void k_sort() {
    int n = blockIdx.x * blockDim.x + threadIdx.x;
    if (n >= NN) return;
    int beg = g_rowptr[n], end = g_rowptr[n + 1];
    int len = end - beg;
    if (len <= 128) {
        int buf[128];
        for (int i = 0; i < len; i++) buf[i] = g_csr[beg + i];
        for (int i = 1; i < len; i++) {
            int v = buf[i];
            int j = i - 1;
            while (j >= 0 && buf[j] > v) { buf[j + 1] = buf[j]; j--; }
            buf[j + 1] = v;
        }
        for (int i = 0; i < len; i++) g_csr[beg + i] = buf[i];
    } else {
        for (int i = beg + 1; i < end; i++) {
            int v = g_csr[i];
            int j = i - 1;
            while (j >= beg && g_csr[j] > v) { g_csr[j + 1] = g_csr[j]; j--; }
            g_csr[j + 1] = v;
        }
    }
}

// ---------------- GEMM: out[M,256] = A[M,64] @ W[256,64]^T (+bias) ----------------
// grid = ((M+127)/128, 4). 128x64 tile, 256 threads, 8x4 per thread, float4 LDS.
__global__ __launch_bounds__(256) void k_gemm(const float* __restrict__ A,
                                              const float* __restrict__ W,
                                              const float* __restrict__ bias,
                                              float* __restrict__ out, int M) {
    __shared__ float xsT[32][132];
    __shared__ float Ws[32][68];
    int tid = threadIdx.x;
    int row0 = blockIdx.x * 128, n0 = blockIdx.y * 64;
    int rg = tid >> 4, cg = tid & 15;
    int r0 = rg * 8, c0 = cg * 4;
    float acc[8][4] = {};

    for (int kc = 0; kc < 64; kc += 32) {
#pragma unroll
        for (int it = 0; it < 4; ++it) {
            int idx = tid + it * 256;
            int r = idx >> 3, k4 = idx & 7;
            int m = row0 + r;
            float4 v = (m < M) ? *(const float4*)(A + (size_t)m * 64 + kc + k4 * 4)
                               : make_float4(0.f, 0.f, 0.f, 0.f);
            xsT[k4 * 4 + 0][r] = v.x; xsT[k4 * 4 + 1][r] = v.y;
            xsT[k4 * 4 + 2][r] = v.z; xsT[k4 * 4 + 3][r] = v.w;
        }
#pragma unroll
        for (int it = 0; it < 2; ++it) {
            int idx = tid + it * 256;
            int n = idx >> 3, k4 = idx & 7;
            float4 v = *(const float4*)(W + (size_t)(n0 + n) * 64 + kc + k4 * 4);
            Ws[k4 * 4 + 0][n] = v.x; Ws[k4 * 4 + 1][n] = v.y;
            Ws[k4 * 4 + 2][n] = v.z; Ws[k4 * 4 + 3][n] = v.w;
        }
        __syncthreads();
#pragma unroll
        for (int k = 0; k < 32; k++) {
            float4 x0 = *(const float4*)&xsT[k][r0];
            float4 x1 = *(const float4*)&xsT[k][r0 + 4];
            float4 wv = *(const float4*)&Ws[k][c0];
            float xv[8] = {x0.x, x0.y, x0.z, x0.w, x1.x, x1.y, x1.z, x1.w};
#pragma unroll
            for (int r = 0; r < 8; r++) {
                acc[r][0] += xv[r] * wv.x; acc[r][1] += xv[r] * wv.y;
                acc[r][2] += xv[r] * wv.z; acc[r][3] += xv[r] * wv.w;
            }
        }
        __syncthreads();
    }
    float4 bv = make_float4(0.f, 0.f, 0.f, 0.f);
    if (bias) bv = *(const float4*)(bias + n0 + c0);
#pragma unroll
    for (int r = 0; r < 8; r++) {
        int m = row0 + r0 + r;
        if (m < M)
            *((float4*)(out + (size_t)m * 256 + n0 + c0)) =
                make_float4(acc[r][0] + bv.x, acc[r][1] + bv.y,
                            acc[r][2] + bv.z, acc[r][3] + bv.w);
    }
}

// ---------------- fused alpha + online softmax + aggregation + self-loop ----------
// warp per dst node. ee-row sum accumulated in-loop; self-loop applied at end
// using eeMean = eeSum/deg (linearity: mean_attr @ We^T == mean of re rows).
__global__ __launch_bounds__(256) void k_fused(const int* __restrict__ ei,
                                               const int* __restrict__ relidx,
                                               const float* __restrict__ att,
                                               const float* __restrict__ bias,
                                               float* __restrict__ out) {
    int w = (blockIdx.x * blockDim.x + threadIdx.x) >> 5;
    int lane = threadIdx.x & 31;
    if (w >= NN) return;
    int beg = g_rowptr[w], end = g_rowptr[w + 1];

    float4 attA = *(const float4*)(att + ((lane >> 4) * 64) + (lane & 15) * 4);
    float4 attB = *(const float4*)(att + 128 + ((lane >> 4) * 64) + (lane & 15) * 4);

    const float* xrp = g_xr + (size_t)w * HC;
    float4 xrA = *(const float4*)(xrp + 4 * lane);
    float4 xrB = *(const float4*)(xrp + 128 + 4 * lane);

    float mA = -CUDART_INF_F, mB = -CUDART_INF_F;
    float sA = 0.f, sB = 0.f;
    float4 accA = make_float4(0.f, 0.f, 0.f, 0.f);
    float4 accB = make_float4(0.f, 0.f, 0.f, 0.f);
    float4 esA = make_float4(0.f, 0.f, 0.f, 0.f);   // ee row sum (for self-loop mean)
    float4 esB = make_float4(0.f, 0.f, 0.f, 0.f);

    for (int i = beg; i < end; i++) {
        int e = g_csr[i];
        int sidx = ei[e];
        const float* eep = g_re + (size_t)relidx[e] * HC;
        const float* xlp = g_xl + (size_t)sidx * HC;
        float4 xlA = *(const float4*)(xlp + 4 * lane);
        float4 xlB = *(const float4*)(xlp + 128 + 4 * lane);
        float4 eeA = *(const float4*)(eep + 4 * lane);
        float4 eeB = *(const float4*)(eep + 128 + 4 * lane);
        esA.x += eeA.x; esA.y += eeA.y; esA.z += eeA.z; esA.w += eeA.w;
        esB.x += eeB.x; esB.y += eeB.y; esB.z += eeB.z; esB.w += eeB.w;

        float t, pA, pB;
        t = xlA.x + xrA.x + eeA.x; t = t > 0.f ? t : 0.2f * t; pA  = t * attA.x;
        t = xlA.y + xrA.y + eeA.y; t = t > 0.f ? t : 0.2f * t; pA += t * attA.y;
        t = xlA.z + xrA.z + eeA.z; t = t > 0.f ? t : 0.2f * t; pA += t * attA.z;
        t = xlA.w + xrA.w + eeA.w; t = t > 0.f ? t : 0.2f * t; pA += t * attA.w;
        t = xlB.x + xrB.x + eeB.x; t = t > 0.f ? t : 0.2f * t; pB  = t * attB.x;
        t = xlB.y + xrB.y + eeB.y; t = t > 0.f ? t : 0.2f * t; pB += t * attB.y;
        t = xlB.z + xrB.z + eeB.z; t = t > 0.f ? t : 0.2f * t; pB += t * attB.z;
        t = xlB.w + xrB.w + eeB.w; t = t > 0.f ? t : 0.2f * t; pB += t * attB.w;
#pragma unroll
        for (int off = 1; off < 16; off <<= 1) {
            pA += __shfl_xor_sync(0xffffffffu, pA, off);
            pB += __shfl_xor_sync(0xffffffffu, pB, off);
        }
        float nm = fmaxf(mA, pA);
        float scl = __expf(mA - nm);
        float wgt = __expf(pA - nm);
        sA = sA * scl + wgt;
        accA.x = accA.x * scl + wgt * xlA.x;
        accA.y = accA.y * scl + wgt * xlA.y;
        accA.z = accA.z * scl + wgt * xlA.z;
        accA.w = accA.w * scl + wgt * xlA.w;
        mA = nm;
        nm = fmaxf(mB, pB);
        scl = __expf(mB - nm);
        wgt = __expf(pB - nm);
        sB = sB * scl + wgt;
        accB.x = accB.x * scl + wgt * xlB.x;
        accB.y = accB.y * scl + wgt * xlB.y;
        accB.z = accB.z * scl + wgt * xlB.z;
        accB.w = accB.w * scl + wgt * xlB.w;
        mB = nm;
    }

    // ---- self-loop: ee = mean of incoming ee rows, xl = xl[w] ----
    {
        int deg = end - beg;
        float inv = 1.f / (float)(deg > 1 ? deg : 1);
        float4 eeA = make_float4(esA.x * inv, esA.y * inv, esA.z * inv, esA.w * inv);
        float4 eeB = make_float4(esB.x * inv, esB.y * inv, esB.z * inv, esB.w * inv);
        const float* xlp = g_xl + (size_t)w * HC;
        float4 xlA = *(const float4*)(xlp + 4 * lane);
        float4 xlB = *(const float4*)(xlp + 128 + 4 * lane);
        float t, pA, pB;
        t = xlA.x + xrA.x + eeA.x; t = t > 0.f ? t : 0.2f * t; pA  = t * attA.x;
        t = xlA.y + xrA.y + eeA.y; t = t > 0.f ? t : 0.2f * t; pA += t * attA.y;
        t = xlA.z + xrA.z + eeA.z; t = t > 0.f ? t : 0.2f * t; pA += t * attA.z;
        t = xlA.w + xrA.w + eeA.w; t = t > 0.f ? t : 0.2f * t; pA += t * attA.w;
        t = xlB.x + xrB.x + eeB.x; t = t > 0.f ? t : 0.2f * t; pB  = t * attB.x;
        t = xlB.y + xrB.y + eeB.y; t = t > 0.f ? t : 0.2f * t; pB += t * attB.y;
        t = xlB.z + xrB.z + eeB.z; t = t > 0.f ? t : 0.2f * t; pB += t * attB.z;
        t = xlB.w + xrB.w + eeB.w; t = t > 0.f ? t : 0.2f * t; pB += t * attB.w;
#pragma unroll
        for (int off = 1; off < 16; off <<= 1) {
            pA += __shfl_xor_sync(0xffffffffu, pA, off);
            pB += __shfl_xor_sync(0xffffffffu, pB, off);
        }
        float nm = fmaxf(mA, pA);
        float scl = __expf(mA - nm);
        float wgt = __expf(pA - nm);
        sA = sA * scl + wgt;
        accA.x = accA.x * scl + wgt * xlA.x;
        accA.y = accA.y * scl + wgt * xlA.y;
        accA.z = accA.z * scl + wgt * xlA.z;
        accA.w = accA.w * scl + wgt * xlA.w;
        nm = fmaxf(mB, pB);
        scl = __expf(mB - nm);
        wgt = __expf(pB - nm);
        sB = sB * scl + wgt;
        accB.x = accB.x * scl + wgt * xlB.x;
        accB.y = accB.y * scl + wgt * xlB.y;
        accB.z = accB.z * scl + wgt * xlB.z;
        accB.w = accB.w * scl + wgt * xlB.w;
    }

    float iA = 1.f / sA, iB = 1.f / sB;
    accA.x *= iA; accA.y *= iA; accA.z *= iA; accA.w *= iA;
    accB.x *= iB; accB.y *= iB; accB.z *= iB; accB.w *= iB;
    accA.x += __shfl_xor_sync(0xffffffffu, accA.x, 16);
    accA.y += __shfl_xor_sync(0xffffffffu, accA.y, 16);
    accA.z += __shfl_xor_sync(0xffffffffu, accA.z, 16);
    accA.w += __shfl_xor_sync(0xffffffffu, accA.w, 16);
    accB.x += __shfl_xor_sync(0xffffffffu, accB.x, 16);
    accB.y += __shfl_xor_sync(0xffffffffu, accB.y, 16);
    accB.z += __shfl_xor_sync(0xffffffffu, accB.z, 16);
    accB.w += __shfl_xor_sync(0xffffffffu, accB.w, 16);
    if (lane < 16) {
        float4 bv = *(const float4*)(bias + 4 * lane);
        float4 o;
        o.x = 0.25f * (accA.x + accB.x) + bv.x;
        o.y = 0.25f * (accA.y + accB.y) + bv.y;
        o.z = 0.25f * (accA.z + accB.z) + bv.z;
        o.w = 0.25f * (accA.w + accB.w) + bv.w;
        *(float4*)(out + (size_t)w * 64 + 4 * lane) = o;
    }
}

// ---------------- host ----------------
extern "C" void kernel_launch(void* const* d_in, const int* in_sizes, int n_in,
                              void* d_out, int out_size) {
    const float* x         = (const float*)d_in[0];
    const int* ei          = (const int*)d_in[1];
    const float* relations = (const float*)d_in[2];
    const int* relidx      = (const int*)d_in[3];
    const float* Wl[2]  = {(const float*)d_in[4],  (const float*)d_in[11]};
    const float* blv[2] = {(const float*)d_in[5],  (const float*)d_in[12]};
    const float* Wr[2]  = {(const float*)d_in[6],  (const float*)d_in[13]};
    const float* brv[2] = {(const float*)d_in[7],  (const float*)d_in[14]};
    const float* We[2]  = {(const float*)d_in[8],  (const float*)d_in[15]};
    const float* att[2] = {(const float*)d_in[9],  (const float*)d_in[16]};
    const float* bo[2]  = {(const float*)d_in[10], (const float*)d_in[17]};

    void *pxl, *pxr, *pre, *ph1;
    cudaGetSymbolAddress(&pxl, g_xl);
    cudaGetSymbolAddress(&pxr, g_xr);
    cudaGetSymbolAddress(&pre, g_re);
    cudaGetSymbolAddress(&ph1, g_h1);

    k_zero<<<(NN + 255) / 256, 256>>>();
    k_count<<<(EE + 255) / 256, 256>>>(ei);
    k_scan<<<1, 1024>>>();
    k_scatter<<<(EE + 255) / 256, 256>>>(ei);
    k_sort<<<(NN + 255) / 256, 256>>>();

    const float* xin = x;
    for (int l = 0; l < 2; l++) {
        dim3 gn((NN + 127) / 128, 4);
        dim3 gr((RT + 127) / 128, 4);
        k_gemm<<<gn, 256>>>(xin, Wl[l], blv[l], (float*)pxl, NN);
        k_gemm<<<gn, 256>>>(xin, Wr[l], brv[l], (float*)pxr, NN);
        k_gemm<<<gr, 256>>>(relations, We[l], nullptr, (float*)pre, RT);
        float* outp = (l == 0) ? (float*)ph1 : (float*)d_out;
        k_fused<<<(NN + 7) / 8, 256>>>(ei, relidx, att[l], bo[l], outp);
        xin = (const float*)ph1;
    }
    if (out_size >= NN * 64 + RT * 64)
        cudaMemcpyAsync((float*)d_out + (size_t)NN * 64, relations,
                        (size_t)RT * 64 * sizeof(float), cudaMemcpyDeviceToDevice);
}

// round 5
// speedup vs baseline: 2.3242x; 1.1900x over previous
#include <cuda_runtime.h>
#include <math_constants.h>

#define NN   20000
#define EE   320000
#define RT   512
#define HC   256      // H*C

// ---------------- scratch (device globals: allocation-free) ----------------
__device__ float g_xl[NN * HC];
__device__ float g_xr[NN * HC];
__device__ float g_re[RT * HC];     // relations @ We^T
__device__ float g_h1[NN * 64];     // layer-0 output
__device__ int   g_deg[NN];
__device__ int   g_rowptr[NN + 1];
__device__ int   g_cursor[NN];
__device__ int   g_csr[EE];

// ---------------- init + CSR build ----------------
__global__ void k_zero() {
    int i = blockIdx.x * blockDim.x + threadIdx.x;
    if (i < NN) { g_deg[i] = 0; g_cursor[i] = 0; }
}

__global__ void k_count(const int* __restrict__ ei) {
    int i = blockIdx.x * blockDim.x + threadIdx.x;
    if (i < EE) atomicAdd(&g_deg[ei[EE + i]], 1);
}

__global__ void k_scan() {
    __shared__ int wsum[32];
    __shared__ int carry;
    int tid = threadIdx.x, lane = tid & 31, wid = tid >> 5;
    if (tid == 0) { carry = 0; g_rowptr[0] = 0; }
    __syncthreads();
    for (int base = 0; base < NN; base += 1024) {
        int i = base + tid;
        int x = (i < NN) ? g_deg[i] : 0;
#pragma unroll
        for (int off = 1; off < 32; off <<= 1) {
            int t = __shfl_up_sync(0xffffffffu, x, off);
            if (lane >= off) x += t;
        }
        if (lane == 31) wsum[wid] = x;
        __syncthreads();
        if (wid == 0) {
            int s = wsum[lane];
#pragma unroll
            for (int off = 1; off < 32; off <<= 1) {
                int t = __shfl_up_sync(0xffffffffu, s, off);
                if (lane >= off) s += t;
            }
            wsum[lane] = s;
        }
        __syncthreads();
        int total = wsum[31];
        int prefix = carry + (wid ? wsum[wid - 1] : 0) + x;
        if (i < NN) g_rowptr[i + 1] = prefix;
        __syncthreads();
        if (tid == 0) carry += total;
        __syncthreads();
    }
}

__global__ void k_scatter(const int* __restrict__ ei) {
    int i = blockIdx.x * blockDim.x + threadIdx.x;
    if (i >= EE) return;
    int d = ei[EE + i];
    int pos = atomicAdd(&g_cursor[d], 1);
    g_csr[g_rowptr[d] + pos] = i;
}

__global__ void k_sort() {
    int n = blockIdx.x * blockDim.x + threadIdx.x;
    if (n >= NN) return;
    int beg = g_rowptr[n], end = g_rowptr[n + 1];
    int len = end - beg;
    if (len <= 128) {
        int buf[128];
        for (int i = 0; i < len; i++) buf[i] = g_csr[beg + i];
        for (int i = 1; i < len; i++) {
            int v = buf[i];
            int j = i - 1;
            while (j >= 0 && buf[j] > v) { buf[j + 1] = buf[j]; j--; }
            buf[j + 1] = v;
        }
        for (int i = 0; i < len; i++) g_csr[beg + i] = buf[i];
    } else {
        for (int i = beg + 1; i < end; i++) {
            int v = g_csr[i];
            int j = i - 1;
            while (j >= beg && g_csr[j] > v) { g_csr[j + 1] = g_csr[j]; j--; }
            g_csr[j + 1] = v;
        }
    }
}

// ---------------- tf32 helpers ----------------
__device__ __forceinline__ unsigned f2tf32(float f) {
    unsigned u;
    asm("cvt.rna.tf32.f32 %0, %1;" : "=r"(u) : "f"(f));
    return u;
}
__device__ __forceinline__ void mma_tf32(float& c0, float& c1, float& c2, float& c3,
                                         unsigned a0, unsigned a1, unsigned a2, unsigned a3,
                                         unsigned b0, unsigned b1) {
    asm("mma.sync.aligned.m16n8k8.row.col.f32.tf32.tf32.f32 "
        "{%0,%1,%2,%3},{%4,%5,%6,%7},{%8,%9},{%0,%1,%2,%3};"
        : "+f"(c0), "+f"(c1), "+f"(c2), "+f"(c3)
        : "r"(a0), "r"(a1), "r"(a2), "r"(a3), "r"(b0), "r"(b1));
}

// ---- tensor-core GEMM: out[M,256] = A[M,64] @ W[256,64]^T + bias ----
// grid = (ceil(M/64), 4, 2); z selects (W0,out0) vs (W1,out1). 64x64 tile,
// 8 warps as 4(row)x2(col), each warp 16 rows x 32 cols via m16n8k8 tf32.
__global__ __launch_bounds__(256) void k_gemm_tc(const float* __restrict__ A,
                                                 const float* __restrict__ W0,
                                                 const float* __restrict__ bias0,
                                                 float* __restrict__ out0,
                                                 const float* __restrict__ W1,
                                                 const float* __restrict__ bias1,
                                                 float* __restrict__ out1, int M) {
    const float* W    = blockIdx.z ? W1 : W0;
    const float* bias = blockIdx.z ? bias1 : bias0;
    float* out        = blockIdx.z ? out1 : out0;
    __shared__ unsigned As[64][68];   // [row][k]
    __shared__ unsigned Ws[64][68];   // [n][k]
    int tid = threadIdx.x;
    int row0 = blockIdx.x * 64, n0 = blockIdx.y * 64;

#pragma unroll
    for (int it = 0; it < 4; it++) {
        int idx = tid + it * 256;         // float4 index 0..1023
        int r = idx >> 4, k4 = idx & 15;
        int m = row0 + r;
        float4 v = (m < M) ? *(const float4*)(A + (size_t)m * 64 + k4 * 4)
                           : make_float4(0.f, 0.f, 0.f, 0.f);
        As[r][k4 * 4 + 0] = f2tf32(v.x); As[r][k4 * 4 + 1] = f2tf32(v.y);
        As[r][k4 * 4 + 2] = f2tf32(v.z); As[r][k4 * 4 + 3] = f2tf32(v.w);
        float4 wv = *(const float4*)(W + (size_t)(n0 + r) * 64 + k4 * 4);
        Ws[r][k4 * 4 + 0] = f2tf32(wv.x); Ws[r][k4 * 4 + 1] = f2tf32(wv.y);
        Ws[r][k4 * 4 + 2] = f2tf32(wv.z); Ws[r][k4 * 4 + 3] = f2tf32(wv.w);
    }
    __syncthreads();

    int wid = tid >> 5, lane = tid & 31;
    int g = lane >> 2, tig = lane & 3;
    int rbase = (wid & 3) * 16;
    int ncb = (wid >> 2) * 32;
    float acc[4][4] = {};
#pragma unroll
    for (int ks = 0; ks < 8; ks++) {
        int k0 = ks * 8;
        unsigned a0 = As[rbase + g][k0 + tig];
        unsigned a1 = As[rbase + g + 8][k0 + tig];
        unsigned a2 = As[rbase + g][k0 + tig + 4];
        unsigned a3 = As[rbase + g + 8][k0 + tig + 4];
#pragma unroll
        for (int nt = 0; nt < 4; nt++) {
            unsigned b0 = Ws[ncb + nt * 8 + g][k0 + tig];
            unsigned b1 = Ws[ncb + nt * 8 + g][k0 + tig + 4];
            mma_tf32(acc[nt][0], acc[nt][1], acc[nt][2], acc[nt][3],
                     a0, a1, a2, a3, b0, b1);
        }
    }
    int m0 = row0 + rbase + g;
#pragma unroll
    for (int nt = 0; nt < 4; nt++) {
        int gcol = n0 + ncb + nt * 8 + tig * 2;
        float2 bv = *(const float2*)(bias + gcol);
        if (m0 < M)
            *(float2*)(out + (size_t)m0 * 256 + gcol) =
                make_float2(acc[nt][0] + bv.x, acc[nt][1] + bv.y);
        if (m0 + 8 < M)
            *(float2*)(out + (size_t)(m0 + 8) * 256 + gcol) =
                make_float2(acc[nt][2] + bv.x, acc[nt][3] + bv.y);
    }
}

// ---------------- scalar fp32 GEMM (for relations @ We^T; keeps ee precise) ----
__global__ __launch_bounds__(256) void k_gemm(const float* __restrict__ A,
                                              const float* __restrict__ W,
                                              const float* __restrict__ bias,
                                              float* __restrict__ out, int M) {
    __shared__ float xsT[32][132];
    __shared__ float Ws[32][68];
    int tid = threadIdx.x;
    int row0 = blockIdx.x * 128, n0 = blockIdx.y * 64;
    int rg = tid >> 4, cg = tid & 15;
    int r0 = rg * 8, c0 = cg * 4;
    float acc[8][4] = {};

    for (int kc = 0; kc < 64; kc += 32) {
#pragma unroll
        for (int it = 0; it < 4; ++it) {
            int idx = tid + it * 256;
            int r = idx >> 3, k4 = idx & 7;
            int m = row0 + r;
            float4 v = (m < M) ? *(const float4*)(A + (size_t)m * 64 + kc + k4 * 4)
                               : make_float4(0.f, 0.f, 0.f, 0.f);
            xsT[k4 * 4 + 0][r] = v.x; xsT[k4 * 4 + 1][r] = v.y;
            xsT[k4 * 4 + 2][r] = v.z; xsT[k4 * 4 + 3][r] = v.w;
        }
#pragma unroll
        for (int it = 0; it < 2; ++it) {
            int idx = tid + it * 256;
            int n = idx >> 3, k4 = idx & 7;
            float4 v = *(const float4*)(W + (size_t)(n0 + n) * 64 + kc + k4 * 4);
            Ws[k4 * 4 + 0][n] = v.x; Ws[k4 * 4 + 1][n] = v.y;
            Ws[k4 * 4 + 2][n] = v.z; Ws[k4 * 4 + 3][n] = v.w;
        }
        __syncthreads();
#pragma unroll
        for (int k = 0; k < 32; k++) {
            float4 x0 = *(const float4*)&xsT[k][r0];
            float4 x1 = *(const float4*)&xsT[k][r0 + 4];
            float4 wv = *(const float4*)&Ws[k][c0];
            float xv[8] = {x0.x, x0.y, x0.z, x0.w, x1.x, x1.y, x1.z, x1.w};
#pragma unroll
            for (int r = 0; r < 8; r++) {
                acc[r][0] += xv[r] * wv.x; acc[r][1] += xv[r] * wv.y;
                acc[r][2] += xv[r] * wv.z; acc[r][3] += xv[r] * wv.w;
            }
        }
        __syncthreads();
    }
    float4 bv = make_float4(0.f, 0.f, 0.f, 0.f);
    if (bias) bv = *(const float4*)(bias + n0 + c0);
#pragma unroll
    for (int r = 0; r < 8; r++) {
        int m = row0 + r0 + r;
        if (m < M)
            *((float4*)(out + (size_t)m * 256 + n0 + c0)) =
                make_float4(acc[r][0] + bv.x, acc[r][1] + bv.y,
                            acc[r][2] + bv.z, acc[r][3] + bv.w);
    }
}

// ---------------- fused alpha + online softmax + aggregation + self-loop ----------
__global__ __launch_bounds__(256) void k_fused(const int* __restrict__ ei,
                                               const int* __restrict__ relidx,
                                               const float* __restrict__ att,
                                               const float* __restrict__ bias,
                                               float* __restrict__ out) {
    int w = (blockIdx.x * blockDim.x + threadIdx.x) >> 5;
    int lane = threadIdx.x & 31;
    if (w >= NN) return;
    int beg = g_rowptr[w], end = g_rowptr[w + 1];

    float4 attA = *(const float4*)(att + ((lane >> 4) * 64) + (lane & 15) * 4);
    float4 attB = *(const float4*)(att + 128 + ((lane >> 4) * 64) + (lane & 15) * 4);

    const float* xrp = g_xr + (size_t)w * HC;
    float4 xrA = *(const float4*)(xrp + 4 * lane);
    float4 xrB = *(const float4*)(xrp + 128 + 4 * lane);

    float mA = -CUDART_INF_F, mB = -CUDART_INF_F;
    float sA = 0.f, sB = 0.f;
    float4 accA = make_float4(0.f, 0.f, 0.f, 0.f);
    float4 accB = make_float4(0.f, 0.f, 0.f, 0.f);
    float4 esA = make_float4(0.f, 0.f, 0.f, 0.f);
    float4 esB = make_float4(0.f, 0.f, 0.f, 0.f);

    for (int i = beg; i < end; i++) {
        int e = g_csr[i];
        int sidx = ei[e];
        const float* eep = g_re + (size_t)relidx[e] * HC;
        const float* xlp = g_xl + (size_t)sidx * HC;
        float4 xlA = *(const float4*)(xlp + 4 * lane);
        float4 xlB = *(const float4*)(xlp + 128 + 4 * lane);
        float4 eeA = *(const float4*)(eep + 4 * lane);
        float4 eeB = *(const float4*)(eep + 128 + 4 * lane);
        esA.x += eeA.x; esA.y += eeA.y; esA.z += eeA.z; esA.w += eeA.w;
        esB.x += eeB.x; esB.y += eeB.y; esB.z += eeB.z; esB.w += eeB.w;

        float t, pA, pB;
        t = xlA.x + xrA.x + eeA.x; t = t > 0.f ? t : 0.2f * t; pA  = t * attA.x;
        t = xlA.y + xrA.y + eeA.y; t = t > 0.f ? t : 0.2f * t; pA += t * attA.y;
        t = xlA.z + xrA.z + eeA.z; t = t > 0.f ? t : 0.2f * t; pA += t * attA.z;
        t = xlA.w + xrA.w + eeA.w; t = t > 0.f ? t : 0.2f * t; pA += t * attA.w;
        t = xlB.x + xrB.x + eeB.x; t = t > 0.f ? t : 0.2f * t; pB  = t * attB.x;
        t = xlB.y + xrB.y + eeB.y; t = t > 0.f ? t : 0.2f * t; pB += t * attB.y;
        t = xlB.z + xrB.z + eeB.z; t = t > 0.f ? t : 0.2f * t; pB += t * attB.z;
        t = xlB.w + xrB.w + eeB.w; t = t > 0.f ? t : 0.2f * t; pB += t * attB.w;
#pragma unroll
        for (int off = 1; off < 16; off <<= 1) {
            pA += __shfl_xor_sync(0xffffffffu, pA, off);
            pB += __shfl_xor_sync(0xffffffffu, pB, off);
        }
        float nm = fmaxf(mA, pA);
        float scl = __expf(mA - nm);
        float wgt = __expf(pA - nm);
        sA = sA * scl + wgt;
        accA.x = accA.x * scl + wgt * xlA.x;
        accA.y = accA.y * scl + wgt * xlA.y;
        accA.z = accA.z * scl + wgt * xlA.z;
        accA.w = accA.w * scl + wgt * xlA.w;
        mA = nm;
        nm = fmaxf(mB, pB);
        scl = __expf(mB - nm);
        wgt = __expf(pB - nm);
        sB = sB * scl + wgt;
        accB.x = accB.x * scl + wgt * xlB.x;
        accB.y = accB.y * scl + wgt * xlB.y;
        accB.z = accB.z * scl + wgt * xlB.z;
        accB.w = accB.w * scl + wgt * xlB.w;
        mB = nm;
    }

    {   // self-loop
        int deg = end - beg;
        float inv = 1.f / (float)(deg > 1 ? deg : 1);
        float4 eeA = make_float4(esA.x * inv, esA.y * inv, esA.z * inv, esA.w * inv);
        float4 eeB = make_float4(esB.x * inv, esB.y * inv, esB.z * inv, esB.w * inv);
        const float* xlp = g_xl + (size_t)w * HC;
        float4 xlA = *(const float4*)(xlp + 4 * lane);
        float4 xlB = *(const float4*)(xlp + 128 + 4 * lane);
        float t, pA, pB;
        t = xlA.x + xrA.x + eeA.x; t = t > 0.f ? t : 0.2f * t; pA  = t * attA.x;
        t = xlA.y + xrA.y + eeA.y; t = t > 0.f ? t : 0.2f * t; pA += t * attA.y;
        t = xlA.z + xrA.z + eeA.z; t = t > 0.f ? t : 0.2f * t; pA += t * attA.z;
        t = xlA.w + xrA.w + eeA.w; t = t > 0.f ? t : 0.2f * t; pA += t * attA.w;
        t = xlB.x + xrB.x + eeB.x; t = t > 0.f ? t : 0.2f * t; pB  = t * attB.x;
        t = xlB.y + xrB.y + eeB.y; t = t > 0.f ? t : 0.2f * t; pB += t * attB.y;
        t = xlB.z + xrB.z + eeB.z; t = t > 0.f ? t : 0.2f * t; pB += t * attB.z;
        t = xlB.w + xrB.w + eeB.w; t = t > 0.f ? t : 0.2f * t; pB += t * attB.w;
#pragma unroll
        for (int off = 1; off < 16; off <<= 1) {
            pA += __shfl_xor_sync(0xffffffffu, pA, off);
            pB += __shfl_xor_sync(0xffffffffu, pB, off);
        }
        float nm = fmaxf(mA, pA);
        float scl = __expf(mA - nm);
        float wgt = __expf(pA - nm);
        sA = sA * scl + wgt;
        accA.x = accA.x * scl + wgt * xlA.x;
        accA.y = accA.y * scl + wgt * xlA.y;
        accA.z = accA.z * scl + wgt * xlA.z;
        accA.w = accA.w * scl + wgt * xlA.w;
        nm = fmaxf(mB, pB);
        scl = __expf(mB - nm);
        wgt = __expf(pB - nm);
        sB = sB * scl + wgt;
        accB.x = accB.x * scl + wgt * xlB.x;
        accB.y = accB.y * scl + wgt * xlB.y;
        accB.z = accB.z * scl + wgt * xlB.z;
        accB.w = accB.w * scl + wgt * xlB.w;
    }

    float iA = 1.f / sA, iB = 1.f / sB;
    accA.x *= iA; accA.y *= iA; accA.z *= iA; accA.w *= iA;
    accB.x *= iB; accB.y *= iB; accB.z *= iB; accB.w *= iB;
    accA.x += __shfl_xor_sync(0xffffffffu, accA.x, 16);
    accA.y += __shfl_xor_sync(0xffffffffu, accA.y, 16);
    accA.z += __shfl_xor_sync(0xffffffffu, accA.z, 16);
    accA.w += __shfl_xor_sync(0xffffffffu, accA.w, 16);
    accB.x += __shfl_xor_sync(0xffffffffu, accB.x, 16);
    accB.y += __shfl_xor_sync(0xffffffffu, accB.y, 16);
    accB.z += __shfl_xor_sync(0xffffffffu, accB.z, 16);
    accB.w += __shfl_xor_sync(0xffffffffu, accB.w, 16);
    if (lane < 16) {
        float4 bv = *(const float4*)(bias + 4 * lane);
        float4 o;
        o.x = 0.25f * (accA.x + accB.x) + bv.x;
        o.y = 0.25f * (accA.y + accB.y) + bv.y;
        o.z = 0.25f * (accA.z + accB.z) + bv.z;
        o.w = 0.25f * (accA.w + accB.w) + bv.w;
        *(float4*)(out + (size_t)w * 64 + 4 * lane) = o;
    }
}

// ---------------- host ----------------
extern "C" void kernel_launch(void* const* d_in, const int* in_sizes, int n_in,
                              void* d_out, int out_size) {
    const float* x         = (const float*)d_in[0];
    const int* ei          = (const int*)d_in[1];
    const float* relations = (const float*)d_in[2];
    const int* relidx      = (const int*)d_in[3];
    const float* Wl[2]  = {(const float*)d_in[4],  (const float*)d_in[11]};
    const float* blv[2] = {(const float*)d_in[5],  (const float*)d_in[12]};
    const float* Wr[2]  = {(const float*)d_in[6],  (const float*)d_in[13]};
    const float* brv[2] = {(const float*)d_in[7],  (const float*)d_in[14]};
    const float* We[2]  = {(const float*)d_in[8],  (const float*)d_in[15]};
    const float* att[2] = {(const float*)d_in[9],  (const float*)d_in[16]};
    const float* bo[2]  = {(const float*)d_in[10], (const float*)d_in[17]};

    void *pxl, *pxr, *pre, *ph1;
    cudaGetSymbolAddress(&pxl, g_xl);
    cudaGetSymbolAddress(&pxr, g_xr);
    cudaGetSymbolAddress(&pre, g_re);
    cudaGetSymbolAddress(&ph1, g_h1);

    k_zero<<<(NN + 255) / 256, 256>>>();
    k_count<<<(EE + 255) / 256, 256>>>(ei);
    k_scan<<<1, 1024>>>();
    k_scatter<<<(EE + 255) / 256, 256>>>(ei);
    k_sort<<<(NN + 255) / 256, 256>>>();

    const float* xin = x;
    for (int l = 0; l < 2; l++) {
        dim3 gtc((NN + 63) / 64, 4, 2);
        dim3 gr((RT + 127) / 128, 4);
        k_gemm_tc<<<gtc, 256>>>(xin, Wl[l], blv[l], (float*)pxl,
                                Wr[l], brv[l], (float*)pxr, NN);
        k_gemm<<<gr, 256>>>(relations, We[l], nullptr, (float*)pre, RT);
        float* outp = (l == 0) ? (float*)ph1 : (float*)d_out;
        k_fused<<<(NN + 7) / 8, 256>>>(ei, relidx, att[l], bo[l], outp);
        xin = (const float*)ph1;
    }
    if (out_size >= NN * 64 + RT * 64)
        cudaMemcpyAsync((float*)d_out + (size_t)NN * 64, relations,
                        (size_t)RT * 64 * sizeof(float), cudaMemcpyDeviceToDevice);
}

// round 6
// speedup vs baseline: 2.4318x; 1.0463x over previous
#include <cuda_runtime.h>
#include <math_constants.h>

#define NN   20000
#define EE   320000
#define RT   512
#define HC   256      // H*C

// ---------------- scratch (device globals: allocation-free) ----------------
__device__ float g_xl[NN * HC];
__device__ float g_xr[NN * HC];
__device__ float g_re[RT * HC];     // relations @ We^T
__device__ float g_h1[NN * 64];     // layer-0 output
__device__ int   g_deg[NN];
__device__ int   g_rowptr[NN + 1];
__device__ int   g_cursor[NN];
__device__ int   g_csr[EE];
__device__ int2  g_srcrel[EE];      // (src, rel) per sorted CSR slot

// ---------------- init + CSR build ----------------
__global__ void k_zero() {
    int i = blockIdx.x * blockDim.x + threadIdx.x;
    if (i < NN) { g_deg[i] = 0; g_cursor[i] = 0; }
}

__global__ void k_count(const int* __restrict__ ei) {
    int i = blockIdx.x * blockDim.x + threadIdx.x;
    if (i < EE) atomicAdd(&g_deg[ei[EE + i]], 1);
}

__global__ void k_scan() {
    __shared__ int wsum[32];
    __shared__ int carry;
    int tid = threadIdx.x, lane = tid & 31, wid = tid >> 5;
    if (tid == 0) { carry = 0; g_rowptr[0] = 0; }
    __syncthreads();
    for (int base = 0; base < NN; base += 1024) {
        int i = base + tid;
        int x = (i < NN) ? g_deg[i] : 0;
#pragma unroll
        for (int off = 1; off < 32; off <<= 1) {
            int t = __shfl_up_sync(0xffffffffu, x, off);
            if (lane >= off) x += t;
        }
        if (lane == 31) wsum[wid] = x;
        __syncthreads();
        if (wid == 0) {
            int s = wsum[lane];
#pragma unroll
            for (int off = 1; off < 32; off <<= 1) {
                int t = __shfl_up_sync(0xffffffffu, s, off);
                if (lane >= off) s += t;
            }
            wsum[lane] = s;
        }
        __syncthreads();
        int total = wsum[31];
        int prefix = carry + (wid ? wsum[wid - 1] : 0) + x;
        if (i < NN) g_rowptr[i + 1] = prefix;
        __syncthreads();
        if (tid == 0) carry += total;
        __syncthreads();
    }
}

__global__ void k_scatter(const int* __restrict__ ei) {
    int i = blockIdx.x * blockDim.x + threadIdx.x;
    if (i >= EE) return;
    int d = ei[EE + i];
    int pos = atomicAdd(&g_cursor[d], 1);
    g_csr[g_rowptr[d] + pos] = i;
}

__global__ void k_sort() {
    int n = blockIdx.x * blockDim.x + threadIdx.x;
    if (n >= NN) return;
    int beg = g_rowptr[n], end = g_rowptr[n + 1];
    int len = end - beg;
    if (len <= 128) {
        int buf[128];
        for (int i = 0; i < len; i++) buf[i] = g_csr[beg + i];
        for (int i = 1; i < len; i++) {
            int v = buf[i];
            int j = i - 1;
            while (j >= 0 && buf[j] > v) { buf[j + 1] = buf[j]; j--; }
            buf[j + 1] = v;
        }
        for (int i = 0; i < len; i++) g_csr[beg + i] = buf[i];
    } else {
        for (int i = beg + 1; i < end; i++) {
            int v = g_csr[i];
            int j = i - 1;
            while (j >= beg && g_csr[j] > v) { g_csr[j + 1] = g_csr[j]; j--; }
            g_csr[j + 1] = v;
        }
    }
}

// pack (src, rel) per sorted CSR slot -> kills the dependent-load chain in k_fused
__global__ void k_pack(const int* __restrict__ ei, const int* __restrict__ relidx) {
    int i = blockIdx.x * blockDim.x + threadIdx.x;
    if (i >= EE) return;
    int e = g_csr[i];
    g_srcrel[i] = make_int2(ei[e], relidx[e]);
}

// ---------------- tf32 helpers ----------------
__device__ __forceinline__ unsigned f2tf32(float f) {
    unsigned u;
    asm("cvt.rna.tf32.f32 %0, %1;" : "=r"(u) : "f"(f));
    return u;
}
__device__ __forceinline__ void mma_tf32(float& c0, float& c1, float& c2, float& c3,
                                         unsigned a0, unsigned a1, unsigned a2, unsigned a3,
                                         unsigned b0, unsigned b1) {
    asm("mma.sync.aligned.m16n8k8.row.col.f32.tf32.tf32.f32 "
        "{%0,%1,%2,%3},{%4,%5,%6,%7},{%8,%9},{%0,%1,%2,%3};"
        : "+f"(c0), "+f"(c1), "+f"(c2), "+f"(c3)
        : "r"(a0), "r"(a1), "r"(a2), "r"(a3), "r"(b0), "r"(b1));
}

// ---- tensor-core GEMM: out[M,256] = A[M,64] @ W[256,64]^T + bias ----
__global__ __launch_bounds__(256) void k_gemm_tc(const float* __restrict__ A,
                                                 const float* __restrict__ W0,
                                                 const float* __restrict__ bias0,
                                                 float* __restrict__ out0,
                                                 const float* __restrict__ W1,
                                                 const float* __restrict__ bias1,
                                                 float* __restrict__ out1, int M) {
    const float* W    = blockIdx.z ? W1 : W0;
    const float* bias = blockIdx.z ? bias1 : bias0;
    float* out        = blockIdx.z ? out1 : out0;
    __shared__ unsigned As[64][68];
    __shared__ unsigned Ws[64][68];
    int tid = threadIdx.x;
    int row0 = blockIdx.x * 64, n0 = blockIdx.y * 64;

#pragma unroll
    for (int it = 0; it < 4; it++) {
        int idx = tid + it * 256;
        int r = idx >> 4, k4 = idx & 15;
        int m = row0 + r;
        float4 v = (m < M) ? *(const float4*)(A + (size_t)m * 64 + k4 * 4)
                           : make_float4(0.f, 0.f, 0.f, 0.f);
        As[r][k4 * 4 + 0] = f2tf32(v.x); As[r][k4 * 4 + 1] = f2tf32(v.y);
        As[r][k4 * 4 + 2] = f2tf32(v.z); As[r][k4 * 4 + 3] = f2tf32(v.w);
        float4 wv = *(const float4*)(W + (size_t)(n0 + r) * 64 + k4 * 4);
        Ws[r][k4 * 4 + 0] = f2tf32(wv.x); Ws[r][k4 * 4 + 1] = f2tf32(wv.y);
        Ws[r][k4 * 4 + 2] = f2tf32(wv.z); Ws[r][k4 * 4 + 3] = f2tf32(wv.w);
    }
    __syncthreads();

    int wid = tid >> 5, lane = tid & 31;
    int g = lane >> 2, tig = lane & 3;
    int rbase = (wid & 3) * 16;
    int ncb = (wid >> 2) * 32;
    float acc[4][4] = {};
#pragma unroll
    for (int ks = 0; ks < 8; ks++) {
        int k0 = ks * 8;
        unsigned a0 = As[rbase + g][k0 + tig];
        unsigned a1 = As[rbase + g + 8][k0 + tig];
        unsigned a2 = As[rbase + g][k0 + tig + 4];
        unsigned a3 = As[rbase + g + 8][k0 + tig + 4];
#pragma unroll
        for (int nt = 0; nt < 4; nt++) {
            unsigned b0 = Ws[ncb + nt * 8 + g][k0 + tig];
            unsigned b1 = Ws[ncb + nt * 8 + g][k0 + tig + 4];
            mma_tf32(acc[nt][0], acc[nt][1], acc[nt][2], acc[nt][3],
                     a0, a1, a2, a3, b0, b1);
        }
    }
    int m0 = row0 + rbase + g;
#pragma unroll
    for (int nt = 0; nt < 4; nt++) {
        int gcol = n0 + ncb + nt * 8 + tig * 2;
        float2 bv = *(const float2*)(bias + gcol);
        if (m0 < M)
            *(float2*)(out + (size_t)m0 * 256 + gcol) =
                make_float2(acc[nt][0] + bv.x, acc[nt][1] + bv.y);
        if (m0 + 8 < M)
            *(float2*)(out + (size_t)(m0 + 8) * 256 + gcol) =
                make_float2(acc[nt][2] + bv.x, acc[nt][3] + bv.y);
    }
}

// ---------------- scalar fp32 GEMM (relations @ We^T; keeps ee precise) ----
__global__ __launch_bounds__(256) void k_gemm(const float* __restrict__ A,
                                              const float* __restrict__ W,
                                              const float* __restrict__ bias,
                                              float* __restrict__ out, int M) {
    __shared__ float xsT[32][132];
    __shared__ float Ws[32][68];
    int tid = threadIdx.x;
    int row0 = blockIdx.x * 128, n0 = blockIdx.y * 64;
    int rg = tid >> 4, cg = tid & 15;
    int r0 = rg * 8, c0 = cg * 4;
    float acc[8][4] = {};

    for (int kc = 0; kc < 64; kc += 32) {
#pragma unroll
        for (int it = 0; it < 4; ++it) {
            int idx = tid + it * 256;
            int r = idx >> 3, k4 = idx & 7;
            int m = row0 + r;
            float4 v = (m < M) ? *(const float4*)(A + (size_t)m * 64 + kc + k4 * 4)
                               : make_float4(0.f, 0.f, 0.f, 0.f);
            xsT[k4 * 4 + 0][r] = v.x; xsT[k4 * 4 + 1][r] = v.y;
            xsT[k4 * 4 + 2][r] = v.z; xsT[k4 * 4 + 3][r] = v.w;
        }
#pragma unroll
        for (int it = 0; it < 2; ++it) {
            int idx = tid + it * 256;
            int n = idx >> 3, k4 = idx & 7;
            float4 v = *(const float4*)(W + (size_t)(n0 + n) * 64 + kc + k4 * 4);
            Ws[k4 * 4 + 0][n] = v.x; Ws[k4 * 4 + 1][n] = v.y;
            Ws[k4 * 4 + 2][n] = v.z; Ws[k4 * 4 + 3][n] = v.w;
        }
        __syncthreads();
#pragma unroll
        for (int k = 0; k < 32; k++) {
            float4 x0 = *(const float4*)&xsT[k][r0];
            float4 x1 = *(const float4*)&xsT[k][r0 + 4];
            float4 wv = *(const float4*)&Ws[k][c0];
            float xv[8] = {x0.x, x0.y, x0.z, x0.w, x1.x, x1.y, x1.z, x1.w};
#pragma unroll
            for (int r = 0; r < 8; r++) {
                acc[r][0] += xv[r] * wv.x; acc[r][1] += xv[r] * wv.y;
                acc[r][2] += xv[r] * wv.z; acc[r][3] += xv[r] * wv.w;
            }
        }
        __syncthreads();
    }
    float4 bv = make_float4(0.f, 0.f, 0.f, 0.f);
    if (bias) bv = *(const float4*)(bias + n0 + c0);
#pragma unroll
    for (int r = 0; r < 8; r++) {
        int m = row0 + r0 + r;
        if (m < M)
            *((float4*)(out + (size_t)m * 256 + n0 + c0)) =
                make_float4(acc[r][0] + bv.x, acc[r][1] + bv.y,
                            acc[r][2] + bv.z, acc[r][3] + bv.w);
    }
}

// ---------------- fused alpha + online softmax + aggregation + self-loop ----------
// warp per dst node; unroll-by-2 with batched shfl reduction; packed (src,rel).
struct Rows { float4 xlA, xlB, eeA, eeB; };

__device__ __forceinline__ void load_rows(Rows& r, int src, int rel, int lane) {
    const float* xlp = g_xl + (size_t)src * HC;
    const float* eep = g_re + (size_t)rel * HC;
    r.xlA = *(const float4*)(xlp + 4 * lane);
    r.xlB = *(const float4*)(xlp + 128 + 4 * lane);
    r.eeA = *(const float4*)(eep + 4 * lane);
    r.eeB = *(const float4*)(eep + 128 + 4 * lane);
}

__device__ __forceinline__ void logits(const Rows& r, float4 xrA, float4 xrB,
                                       float4 attA, float4 attB,
                                       float& pA, float& pB) {
    float t;
    t = r.xlA.x + xrA.x + r.eeA.x; t = t > 0.f ? t : 0.2f * t; pA  = t * attA.x;
    t = r.xlA.y + xrA.y + r.eeA.y; t = t > 0.f ? t : 0.2f * t; pA += t * attA.y;
    t = r.xlA.z + xrA.z + r.eeA.z; t = t > 0.f ? t : 0.2f * t; pA += t * attA.z;
    t = r.xlA.w + xrA.w + r.eeA.w; t = t > 0.f ? t : 0.2f * t; pA += t * attA.w;
    t = r.xlB.x + xrB.x + r.eeB.x; t = t > 0.f ? t : 0.2f * t; pB  = t * attB.x;
    t = r.xlB.y + xrB.y + r.eeB.y; t = t > 0.f ? t : 0.2f * t; pB += t * attB.y;
    t = r.xlB.z + xrB.z + r.eeB.z; t = t > 0.f ? t : 0.2f * t; pB += t * attB.z;
    t = r.xlB.w + xrB.w + r.eeB.w; t = t > 0.f ? t : 0.2f * t; pB += t * attB.w;
}

__device__ __forceinline__ void online_update(float pA, float pB, const Rows& r,
                                              float& mA, float& mB, float& sA, float& sB,
                                              float4& accA, float4& accB) {
    float nm = fmaxf(mA, pA);
    float scl = __expf(mA - nm);
    float wgt = __expf(pA - nm);
    sA = sA * scl + wgt;
    accA.x = accA.x * scl + wgt * r.xlA.x;
    accA.y = accA.y * scl + wgt * r.xlA.y;
    accA.z = accA.z * scl + wgt * r.xlA.z;
    accA.w = accA.w * scl + wgt * r.xlA.w;
    mA = nm;
    nm = fmaxf(mB, pB);
    scl = __expf(mB - nm);
    wgt = __expf(pB - nm);
    sB = sB * scl + wgt;
    accB.x = accB.x * scl + wgt * r.xlB.x;
    accB.y = accB.y * scl + wgt * r.xlB.y;
    accB.z = accB.z * scl + wgt * r.xlB.z;
    accB.w = accB.w * scl + wgt * r.xlB.w;
    mB = nm;
}

__global__ __launch_bounds__(256) void k_fused(const float* __restrict__ att,
                                               const float* __restrict__ bias,
                                               float* __restrict__ out) {
    int w = (blockIdx.x * blockDim.x + threadIdx.x) >> 5;
    int lane = threadIdx.x & 31;
    if (w >= NN) return;
    int beg = g_rowptr[w], end = g_rowptr[w + 1];

    float4 attA = *(const float4*)(att + ((lane >> 4) * 64) + (lane & 15) * 4);
    float4 attB = *(const float4*)(att + 128 + ((lane >> 4) * 64) + (lane & 15) * 4);

    const float* xrp = g_xr + (size_t)w * HC;
    float4 xrA = *(const float4*)(xrp + 4 * lane);
    float4 xrB = *(const float4*)(xrp + 128 + 4 * lane);

    float mA = -CUDART_INF_F, mB = -CUDART_INF_F;
    float sA = 0.f, sB = 0.f;
    float4 accA = make_float4(0.f, 0.f, 0.f, 0.f);
    float4 accB = make_float4(0.f, 0.f, 0.f, 0.f);
    float4 esA = make_float4(0.f, 0.f, 0.f, 0.f);
    float4 esB = make_float4(0.f, 0.f, 0.f, 0.f);

    int i = beg;
    for (; i + 2 <= end; i += 2) {
        int2 sr0 = g_srcrel[i];
        int2 sr1 = g_srcrel[i + 1];
        Rows r0, r1;
        load_rows(r0, sr0.x, sr0.y, lane);
        load_rows(r1, sr1.x, sr1.y, lane);
        // es accumulation in index order
        esA.x += r0.eeA.x; esA.y += r0.eeA.y; esA.z += r0.eeA.z; esA.w += r0.eeA.w;
        esB.x += r0.eeB.x; esB.y += r0.eeB.y; esB.z += r0.eeB.z; esB.w += r0.eeB.w;
        esA.x += r1.eeA.x; esA.y += r1.eeA.y; esA.z += r1.eeA.z; esA.w += r1.eeA.w;
        esB.x += r1.eeB.x; esB.y += r1.eeB.y; esB.z += r1.eeB.z; esB.w += r1.eeB.w;

        float p0A, p0B, p1A, p1B;
        logits(r0, xrA, xrB, attA, attB, p0A, p0B);
        logits(r1, xrA, xrB, attA, attB, p1A, p1B);
        // batched reduction: 4 independent shfl chains, pipelined
#pragma unroll
        for (int off = 1; off < 16; off <<= 1) {
            p0A += __shfl_xor_sync(0xffffffffu, p0A, off);
            p0B += __shfl_xor_sync(0xffffffffu, p0B, off);
            p1A += __shfl_xor_sync(0xffffffffu, p1A, off);
            p1B += __shfl_xor_sync(0xffffffffu, p1B, off);
        }
        online_update(p0A, p0B, r0, mA, mB, sA, sB, accA, accB);
        online_update(p1A, p1B, r1, mA, mB, sA, sB, accA, accB);
    }
    if (i < end) {
        int2 sr = g_srcrel[i];
        Rows r;
        load_rows(r, sr.x, sr.y, lane);
        esA.x += r.eeA.x; esA.y += r.eeA.y; esA.z += r.eeA.z; esA.w += r.eeA.w;
        esB.x += r.eeB.x; esB.y += r.eeB.y; esB.z += r.eeB.z; esB.w += r.eeB.w;
        float pA, pB;
        logits(r, xrA, xrB, attA, attB, pA, pB);
#pragma unroll
        for (int off = 1; off < 16; off <<= 1) {
            pA += __shfl_xor_sync(0xffffffffu, pA, off);
            pB += __shfl_xor_sync(0xffffffffu, pB, off);
        }
        online_update(pA, pB, r, mA, mB, sA, sB, accA, accB);
    }

    {   // self-loop: ee = mean of incoming ee rows, xl = xl[w]
        int deg = end - beg;
        float inv = 1.f / (float)(deg > 1 ? deg : 1);
        Rows r;
        r.eeA = make_float4(esA.x * inv, esA.y * inv, esA.z * inv, esA.w * inv);
        r.eeB = make_float4(esB.x * inv, esB.y * inv, esB.z * inv, esB.w * inv);
        const float* xlp = g_xl + (size_t)w * HC;
        r.xlA = *(const float4*)(xlp + 4 * lane);
        r.xlB = *(const float4*)(xlp + 128 + 4 * lane);
        float pA, pB;
        logits(r, xrA, xrB, attA, attB, pA, pB);
#pragma unroll
        for (int off = 1; off < 16; off <<= 1) {
            pA += __shfl_xor_sync(0xffffffffu, pA, off);
            pB += __shfl_xor_sync(0xffffffffu, pB, off);
        }
        online_update(pA, pB, r, mA, mB, sA, sB, accA, accB);
    }

    float iA = 1.f / sA, iB = 1.f / sB;
    accA.x *= iA; accA.y *= iA; accA.z *= iA; accA.w *= iA;
    accB.x *= iB; accB.y *= iB; accB.z *= iB; accB.w *= iB;
    accA.x += __shfl_xor_sync(0xffffffffu, accA.x, 16);
    accA.y += __shfl_xor_sync(0xffffffffu, accA.y, 16);
    accA.z += __shfl_xor_sync(0xffffffffu, accA.z, 16);
    accA.w += __shfl_xor_sync(0xffffffffu, accA.w, 16);
    accB.x += __shfl_xor_sync(0xffffffffu, accB.x, 16);
    accB.y += __shfl_xor_sync(0xffffffffu, accB.y, 16);
    accB.z += __shfl_xor_sync(0xffffffffu, accB.z, 16);
    accB.w += __shfl_xor_sync(0xffffffffu, accB.w, 16);
    if (lane < 16) {
        float4 bv = *(const float4*)(bias + 4 * lane);
        float4 o;
        o.x = 0.25f * (accA.x + accB.x) + bv.x;
        o.y = 0.25f * (accA.y + accB.y) + bv.y;
        o.z = 0.25f * (accA.z + accB.z) + bv.z;
        o.w = 0.25f * (accA.w + accB.w) + bv.w;
        *(float4*)(out + (size_t)w * 64 + 4 * lane) = o;
    }
}

// ---------------- host ----------------
extern "C" void kernel_launch(void* const* d_in, const int* in_sizes, int n_in,
                              void* d_out, int out_size) {
    const float* x         = (const float*)d_in[0];
    const int* ei          = (const int*)d_in[1];
    const float* relations = (const float*)d_in[2];
    const int* relidx      = (const int*)d_in[3];
    const float* Wl[2]  = {(const float*)d_in[4],  (const float*)d_in[11]};
    const float* blv[2] = {(const float*)d_in[5],  (const float*)d_in[12]};
    const float* Wr[2]  = {(const float*)d_in[6],  (const float*)d_in[13]};
    const float* brv[2] = {(const float*)d_in[7],  (const float*)d_in[14]};
    const float* We[2]  = {(const float*)d_in[8],  (const float*)d_in[15]};
    const float* att[2] = {(const float*)d_in[9],  (const float*)d_in[16]};
    const float* bo[2]  = {(const float*)d_in[10], (const float*)d_in[17]};

    void *pxl, *pxr, *pre, *ph1;
    cudaGetSymbolAddress(&pxl, g_xl);
    cudaGetSymbolAddress(&pxr, g_xr);
    cudaGetSymbolAddress(&pre, g_re);
    cudaGetSymbolAddress(&ph1, g_h1);

    k_zero<<<(NN + 255) / 256, 256>>>();
    k_count<<<(EE + 255) / 256, 256>>>(ei);
    k_scan<<<1, 1024>>>();
    k_scatter<<<(EE + 255) / 256, 256>>>(ei);
    k_sort<<<(NN + 255) / 256, 256>>>();
    k_pack<<<(EE + 255) / 256, 256>>>(ei, relidx);

    const float* xin = x;
    for (int l = 0; l < 2; l++) {
        dim3 gtc((NN + 63) / 64, 4, 2);
        dim3 gr((RT + 127) / 128, 4);
        k_gemm_tc<<<gtc, 256>>>(xin, Wl[l], blv[l], (float*)pxl,
                                Wr[l], brv[l], (float*)pxr, NN);
        k_gemm<<<gr, 256>>>(relations, We[l], nullptr, (float*)pre, RT);
        float* outp = (l == 0) ? (float*)ph1 : (float*)d_out;
        k_fused<<<(NN + 7) / 8, 256>>>(att[l], bo[l], outp);
        xin = (const float*)ph1;
    }
    if (out_size >= NN * 64 + RT * 64)
        cudaMemcpyAsync((float*)d_out + (size_t)NN * 64, relations,
                        (size_t)RT * 64 * sizeof(float), cudaMemcpyDeviceToDevice);
}